// round 14
// baseline (speedup 1.0000x reference)
#include <cuda_runtime.h>

// Problem constants (fixed by setup_inputs)
#define BATCH 8
#define P 1024
#define Q 1024
#define HXR (P-2)   // 1022
#define HXC (Q-1)   // 1023
#define HYR (P-1)   // 1023
#define HYC (Q-2)   // 1022

#define TX 32       // tile cols (blockDim.x)
#define WY 8        // blockDim.y
#define KY 4        // outputs per thread (y)
#define TROWS (WY*KY)   // 32 tile rows
#define NT (TX*WY)      // 256 threads

// KF = 0.5 * [-11/6, 3, -3/2, 1/3] ; KB = -0.5 * reversed
#define KF0 (-11.0f/12.0f)
#define KF1 ( 1.5f)
#define KF2 (-0.75f)
#define KF3 ( 1.0f/6.0f)
#define KB0 (-1.0f/6.0f)
#define KB1 ( 0.75f)
#define KB2 (-1.5f)
#define KB3 ( 11.0f/12.0f)

// ===========================================================================
// amper: E_out[y,x] = E[y,x] + S1(Hy) - S2(Hx)
// Thread (tx,ty): col x = x0+tx, rows y = Y..Y+3, Y = y0 + 4*ty.
// Direct L1 loads; no shared memory, no barrier.
// ===========================================================================
__global__ __launch_bounds__(NT) void amper_ldg(
    const float* __restrict__ E,  int Eb,
    const float* __restrict__ Hx, int Hxb,
    const float* __restrict__ Hy, int Hyb,
    const float* __restrict__ filt,
    float* __restrict__ Eout, int Eob)
{
    const int x0 = blockIdx.x * TX;
    const int y0 = blockIdx.y * TROWS;
    const int b  = blockIdx.z;
    const int tx = threadIdx.x, ty = threadIdx.y;

    float f[3][4];
    #pragma unroll
    for (int i = 0; i < 12; ++i) (&f[0][0])[i] = __ldg(filt + i);

    const float* hy = Hy + b * Hyb;
    const float* hx = Hx + b * Hxb;

    const int Y = y0 + ty * KY;
    const int x = x0 + tx;

    const bool interior = (y0 >= 4) && (y0 + TROWS <= P - 4) &&
                          (x0 >= 2) && (x0 + TX <= Q - 2);

    float acc[KY] = {0.f, 0.f, 0.f, 0.f};

    if (interior) {
        const float hh[8] = {
            KB0, KB1,
            0.5f*f[1][0] + KB2, 0.5f*f[1][1] + KB3,
            0.5f*f[1][2] + KF0, 0.5f*f[1][3] + KF1,
            KF2, KF3
        };
        float w0[4], w2[4];
        #pragma unroll
        for (int d = 0; d < 4; ++d) { w0[d] = 0.5f*f[0][d]; w2[d] = 0.5f*f[2][d]; }

        // ---- S1 (Hy), column-wise, added ----
        {   // col x-2, rows Y-2..Y+4
            float v[KY+3];
            #pragma unroll
            for (int t = 0; t < KY+3; ++t) v[t] = __ldg(hy + (Y-2+t) * HYC + (x-2));
            #pragma unroll
            for (int m = 0; m < KY; ++m)
                #pragma unroll
                for (int d = 0; d < 4; ++d) acc[m] += w0[d]*v[m+d];
        }
        {   // col x-1, rows Y-4..Y+6 (8-tap)
            float v[KY+7];
            #pragma unroll
            for (int t = 0; t < KY+7; ++t) v[t] = __ldg(hy + (Y-4+t) * HYC + (x-1));
            #pragma unroll
            for (int m = 0; m < KY; ++m)
                #pragma unroll
                for (int t = 0; t < 8; ++t) acc[m] += hh[t]*v[m+t];
        }
        {   // col x, rows Y-2..Y+4
            float v[KY+3];
            #pragma unroll
            for (int t = 0; t < KY+3; ++t) v[t] = __ldg(hy + (Y-2+t) * HYC + x);
            #pragma unroll
            for (int m = 0; m < KY; ++m)
                #pragma unroll
                for (int d = 0; d < 4; ++d) acc[m] += w2[d]*v[m+d];
        }

        // ---- S2 (Hx), row-wise, subtracted ----
        {   // row Y-2: w0 over cols x-2..x+1 (output m=0 only)
            #pragma unroll
            for (int d = 0; d < 4; ++d)
                acc[0] -= w0[d] * __ldg(hx + (Y-2) * HXC + (x-2+d));
        }
        #pragma unroll
        for (int ro = -1; ro <= 2; ++ro) {   // rows Y-1..Y+2, cols x-4..x+3
            float v[8];
            #pragma unroll
            for (int t = 0; t < 8; ++t) v[t] = __ldg(hx + (Y+ro) * HXC + (x-4+t));
            const int m8 = ro + 1;
            #pragma unroll
            for (int t = 0; t < 8; ++t) acc[m8] -= hh[t]*v[t];
            if (ro <= 1) {
                #pragma unroll
                for (int d = 0; d < 4; ++d) acc[ro+2] -= w0[d]*v[d+2];
            }
            if (ro >= 0) {
                #pragma unroll
                for (int d = 0; d < 4; ++d) acc[ro] -= w2[d]*v[d+2];
            }
        }
        {   // row Y+3: w2 over cols x-2..x+1 (output m=3 only)
            #pragma unroll
            for (int d = 0; d < 4; ++d)
                acc[3] -= w2[d] * __ldg(hx + (Y+3) * HXC + (x-2+d));
        }
    } else {
        const float kf[4] = {KF0, KF1, KF2, KF3};
        const float kb[4] = {KB0, KB1, KB2, KB3};
        #pragma unroll
        for (int m = 0; m < KY; ++m) {
            const int y = Y + m;
            float s = 0.0f;
            // S1
            if (y >= 2 && y <= P-3 && x >= 2 && x <= Q-3) {
                float a = 0.0f;
                #pragma unroll
                for (int di = 0; di < 4; ++di)
                    #pragma unroll
                    for (int dj = 0; dj < 3; ++dj)
                        a += __ldg(hy + (y-2+di) * HYC + (x-2+dj)) * f[dj][di];
                s += 0.5f * a;
            }
            if (x >= 1 && x <= Q-2) {
                if (y <= P-5) {
                    float t = 0.0f;
                    #pragma unroll
                    for (int d = 0; d < 4; ++d) t += __ldg(hy + (y+d) * HYC + (x-1)) * kf[d];
                    s += t;
                }
                if (y >= 4) {
                    float t = 0.0f;
                    #pragma unroll
                    for (int d = 0; d < 4; ++d) t += __ldg(hy + (y-4+d) * HYC + (x-1)) * kb[d];
                    s += t;
                }
            }
            // S2
            if (y >= 2 && y <= P-3 && x >= 2 && x <= Q-3) {
                float a = 0.0f;
                #pragma unroll
                for (int di = 0; di < 3; ++di)
                    #pragma unroll
                    for (int dj = 0; dj < 4; ++dj)
                        a += __ldg(hx + (y-2+di) * HXC + (x-2+dj)) * f[di][dj];
                s -= 0.5f * a;
            }
            if (y >= 1 && y <= P-2) {
                if (x <= Q-5) {
                    float t = 0.0f;
                    #pragma unroll
                    for (int d = 0; d < 4; ++d) t += __ldg(hx + (y-1) * HXC + (x+d)) * kf[d];
                    s -= t;
                }
                if (x >= 4) {
                    float t = 0.0f;
                    #pragma unroll
                    for (int d = 0; d < 4; ++d) t += __ldg(hx + (y-1) * HXC + (x-4+d)) * kb[d];
                    s -= t;
                }
            }
            acc[m] = s;
        }
    }

    const float* e = E + b * Eb;
    float* eo = Eout + b * Eob;
    #pragma unroll
    for (int m = 0; m < KY; ++m)
        eo[(Y+m) * Q + x] = __ldg(e + (Y+m) * Q + x) + acc[m];
}

// ===========================================================================
// faraday: Hx_out[i,j] = Hx[i,j] - S3(E);  Hy_out[i,j] = Hy[i,j] + S4(E)
// Thread (tx,ty): col j = j0+tx, rows i = I..I+3, I = i0 + 4*ty.
// ===========================================================================
__global__ __launch_bounds__(NT) void faraday_ldg(
    const float* __restrict__ E,  int Eb,
    const float* __restrict__ Hx, int Hxb,
    const float* __restrict__ Hy, int Hyb,
    const float* __restrict__ filt,
    float* __restrict__ Hxo, int Hxob,
    float* __restrict__ Hyo, int Hyob)
{
    const int j0 = blockIdx.x * TX;
    const int i0 = blockIdx.y * TROWS;
    const int b  = blockIdx.z;
    const int tx = threadIdx.x, ty = threadIdx.y;

    float f[3][4];
    #pragma unroll
    for (int i = 0; i < 12; ++i) (&f[0][0])[i] = __ldg(filt + i);

    const float* e = E + b * Eb;

    const int I = i0 + ty * KY;
    const int j = j0 + tx;

    const bool interior = (i0 >= 2) && (i0 + TROWS <= P - 3) &&
                          (j0 >= 2) && (j0 + TX <= Q - 3);

    if (interior) {
        const float gg[6] = {
            KB0,
            0.5f*f[1][0] + KB1,
            0.5f*f[1][1] + KF0 + KB2,
            0.5f*f[1][2] + KF1 + KB3,
            0.5f*f[1][3] + KF2,
            KF3
        };
        float w0[4], w2[4];
        #pragma unroll
        for (int d = 0; d < 4; ++d) { w0[d] = 0.5f*f[0][d]; w2[d] = 0.5f*f[2][d]; }

        float aHx[KY] = {0.f,0.f,0.f,0.f};
        float aHy[KY] = {0.f,0.f,0.f,0.f};

        {   // col j-2: rows I..I+5
            float v[KY+2];
            #pragma unroll
            for (int t = 0; t < KY+2; ++t) v[t] = __ldg(e + (I+t) * Q + (j-2));
            #pragma unroll
            for (int m = 0; m < KY; ++m) aHx[m] += gg[0]*v[m+1];
        }
        {   // col j-1: rows I..I+5
            float v[KY+2];
            #pragma unroll
            for (int t = 0; t < KY+2; ++t) v[t] = __ldg(e + (I+t) * Q + (j-1));
            #pragma unroll
            for (int m = 0; m < KY; ++m)
                aHx[m] += gg[1]*v[m+1] + w0[0]*v[m] + w2[0]*v[m+2];
        }
        {   // col j: rows I-1..I+5
            float v[KY+3];
            #pragma unroll
            for (int t = 0; t < KY+3; ++t) v[t] = __ldg(e + (I-1+t) * Q + j);
            #pragma unroll
            for (int m = 0; m < KY; ++m) {
                aHx[m] += gg[2]*v[m+2] + w0[1]*v[m+1] + w2[1]*v[m+3];
                #pragma unroll
                for (int d = 0; d < 4; ++d) aHy[m] += w0[d]*v[m+d];
            }
        }
        {   // col j+1: rows I-2..I+6
            float v[KY+5];
            #pragma unroll
            for (int t = 0; t < KY+5; ++t) v[t] = __ldg(e + (I-2+t) * Q + (j+1));
            #pragma unroll
            for (int m = 0; m < KY; ++m) {
                aHx[m] += gg[3]*v[m+3] + w0[2]*v[m+2] + w2[2]*v[m+4];
                #pragma unroll
                for (int t = 0; t < 6; ++t) aHy[m] += gg[t]*v[m+t];
            }
        }
        {   // col j+2: rows I-1..I+5
            float v[KY+3];
            #pragma unroll
            for (int t = 0; t < KY+3; ++t) v[t] = __ldg(e + (I-1+t) * Q + (j+2));
            #pragma unroll
            for (int m = 0; m < KY; ++m) {
                aHx[m] += gg[4]*v[m+2] + w0[3]*v[m+1] + w2[3]*v[m+3];
                #pragma unroll
                for (int d = 0; d < 4; ++d) aHy[m] += w2[d]*v[m+d];
            }
        }
        {   // col j+3: rows I..I+5
            float v[KY+2];
            #pragma unroll
            for (int t = 0; t < KY+2; ++t) v[t] = __ldg(e + (I+t) * Q + (j+3));
            #pragma unroll
            for (int m = 0; m < KY; ++m) aHx[m] += gg[5]*v[m+1];
        }

        const float* hxi = Hx + b * Hxb;
        const float* hyi = Hy + b * Hyb;
        float* hxo = Hxo + b * Hxob;
        float* hyo = Hyo + b * Hyob;
        #pragma unroll
        for (int m = 0; m < KY; ++m) {
            const int i = I + m;
            hxo[i * HXC + j] = __ldg(hxi + i * HXC + j) - aHx[m];
            hyo[i * HYC + j] = __ldg(hyi + i * HYC + j) + aHy[m];
        }
    } else {
        const float kf[4] = {KF0, KF1, KF2, KF3};
        const float kb[4] = {KB0, KB1, KB2, KB3};
        #pragma unroll
        for (int m = 0; m < KY; ++m) {
            const int i = I + m;
            // Hx update: i in [0,HXR), j in [0,HXC)
            if (i < HXR && j < HXC) {
                float s = __ldg(Hx + b * Hxb + i * HXC + j);
                if (j >= 1 && j <= Q-3) {
                    float a = 0.0f;
                    #pragma unroll
                    for (int di = 0; di < 3; ++di)
                        #pragma unroll
                        for (int dj = 0; dj < 4; ++dj)
                            a += __ldg(e + (i+di) * Q + (j-1+dj)) * f[di][dj];
                    s -= 0.5f * a;
                }
                if (j <= Q-4) {
                    float t = 0.0f;
                    #pragma unroll
                    for (int d = 0; d < 4; ++d) t += __ldg(e + (i+1) * Q + (j+d)) * kf[d];
                    s -= t;
                }
                if (j >= 2) {
                    float t = 0.0f;
                    #pragma unroll
                    for (int d = 0; d < 4; ++d) t += __ldg(e + (i+1) * Q + (j-2+d)) * kb[d];
                    s -= t;
                }
                Hxo[b * Hxob + i * HXC + j] = s;
            }
            // Hy update: i in [0,HYR), j in [0,HYC)
            if (i < HYR && j < HYC) {
                float s = __ldg(Hy + b * Hyb + i * HYC + j);
                if (i >= 1 && i <= P-3) {
                    float a = 0.0f;
                    #pragma unroll
                    for (int di = 0; di < 4; ++di)
                        #pragma unroll
                        for (int dj = 0; dj < 3; ++dj)
                            a += __ldg(e + (i-1+di) * Q + (j+dj)) * f[dj][di];
                    s += 0.5f * a;
                }
                if (i <= P-4) {
                    float t = 0.0f;
                    #pragma unroll
                    for (int d = 0; d < 4; ++d) t += __ldg(e + (i+d) * Q + (j+1)) * kf[d];
                    s += t;
                }
                if (i >= 2) {
                    float t = 0.0f;
                    #pragma unroll
                    for (int d = 0; d < 4; ++d) t += __ldg(e + (i-2+d) * Q + (j+1)) * kb[d];
                    s += t;
                }
                Hyo[b * Hyob + i * HYC + j] = s;
            }
        }
    }
}

// ---------------------------------------------------------------------------
// Launch: 2 time steps, results written directly into d_out sections.
// d_out layout:
//   E  : BATCH x (2*P) x Q       @ 0
//   Hx : BATCH x (2*HXR) x HXC   @ BATCH*2*P*Q
//   Hy : BATCH x (2*HYR) x HYC   @ BATCH*2*P*Q + BATCH*2*HXR*HXC
// ---------------------------------------------------------------------------
extern "C" void kernel_launch(void* const* d_in, const int* in_sizes, int n_in,
                              void* d_out, int out_size)
{
    const float* E    = (const float*)d_in[0];
    const float* Hx   = (const float*)d_in[1];
    const float* Hy   = (const float*)d_in[2];
    const float* filt = (const float*)d_in[3];
    float* out = (float*)d_out;

    const int E_IN_B  = P * Q;
    const int HX_IN_B = HXR * HXC;
    const int HY_IN_B = HYR * HYC;

    const int E_OUT_B  = 2 * P * Q;
    const int HX_OUT_B = 2 * HXR * HXC;
    const int HY_OUT_B = 2 * HYR * HYC;

    float* En  = out;
    float* Em  = out + P * Q;
    float* Hxn = out + (long long)BATCH * E_OUT_B;
    float* Hxm = Hxn + HXR * HXC;
    float* Hyn = Hxn + (long long)BATCH * HX_OUT_B;
    float* Hym = Hyn + HYR * HYC;

    dim3 blk(TX, WY, 1);
    dim3 g(Q / TX, P / TROWS, BATCH);   // (32, 32, 8)

    // Step 1
    amper_ldg<<<g, blk>>>(E, E_IN_B, Hx, HX_IN_B, Hy, HY_IN_B, filt,
                          En, E_OUT_B);
    faraday_ldg<<<g, blk>>>(En, E_OUT_B, Hx, HX_IN_B, Hy, HY_IN_B, filt,
                            Hxn, HX_OUT_B, Hyn, HY_OUT_B);
    // Step 2
    amper_ldg<<<g, blk>>>(En, E_OUT_B, Hxn, HX_OUT_B, Hyn, HY_OUT_B, filt,
                          Em, E_OUT_B);
    faraday_ldg<<<g, blk>>>(Em, E_OUT_B, Hxn, HX_OUT_B, Hyn, HY_OUT_B, filt,
                            Hxm, HX_OUT_B, Hym, HY_OUT_B);
}

// round 15
// speedup vs baseline: 1.0013x; 1.0013x over previous
#include <cuda_runtime.h>

// Problem constants (fixed by setup_inputs)
#define BATCH 8
#define P 1024
#define Q 1024
#define HXR (P-2)   // 1022
#define HXC (Q-1)   // 1023
#define HYR (P-1)   // 1023
#define HYC (Q-2)   // 1022

#define TX 32       // tile cols (blockDim.x)
#define WY 8        // blockDim.y
#define KY 4        // outputs per thread (y)
#define TROWS (WY*KY)   // 32 tile rows
#define NT (TX*WY)      // 256 threads

// KF = 0.5 * [-11/6, 3, -3/2, 1/3] ; KB = -0.5 * reversed
#define KF0 (-11.0f/12.0f)
#define KF1 ( 1.5f)
#define KF2 (-0.75f)
#define KF3 ( 1.0f/6.0f)
#define KB0 (-1.0f/6.0f)
#define KB1 ( 0.75f)
#define KB2 (-1.5f)
#define KB3 ( 11.0f/12.0f)

// ===========================================================================
// amper: E_out[y,x] = E[y,x] + S1(Hy) - S2(Hx)
// Thread (tx,ty): col x = x0+tx, rows y = Y..Y+3, Y = y0 + 4*ty.
// Direct L1 loads; no shared memory, no barrier.
// ===========================================================================
__global__ __launch_bounds__(NT) void amper_ldg(
    const float* __restrict__ E,  int Eb,
    const float* __restrict__ Hx, int Hxb,
    const float* __restrict__ Hy, int Hyb,
    const float* __restrict__ filt,
    float* __restrict__ Eout, int Eob)
{
    const int x0 = blockIdx.x * TX;
    const int y0 = blockIdx.y * TROWS;
    const int b  = blockIdx.z;
    const int tx = threadIdx.x, ty = threadIdx.y;

    float f[3][4];
    #pragma unroll
    for (int i = 0; i < 12; ++i) (&f[0][0])[i] = __ldg(filt + i);

    const float* hy = Hy + b * Hyb;
    const float* hx = Hx + b * Hxb;

    const int Y = y0 + ty * KY;
    const int x = x0 + tx;

    const bool interior = (y0 >= 4) && (y0 + TROWS <= P - 4) &&
                          (x0 >= 2) && (x0 + TX <= Q - 2);

    float acc[KY] = {0.f, 0.f, 0.f, 0.f};

    if (interior) {
        const float hh[8] = {
            KB0, KB1,
            0.5f*f[1][0] + KB2, 0.5f*f[1][1] + KB3,
            0.5f*f[1][2] + KF0, 0.5f*f[1][3] + KF1,
            KF2, KF3
        };
        float w0[4], w2[4];
        #pragma unroll
        for (int d = 0; d < 4; ++d) { w0[d] = 0.5f*f[0][d]; w2[d] = 0.5f*f[2][d]; }

        // ---- S1 (Hy), column-wise, added ----
        {   // col x-2, rows Y-2..Y+4
            float v[KY+3];
            #pragma unroll
            for (int t = 0; t < KY+3; ++t) v[t] = __ldg(hy + (Y-2+t) * HYC + (x-2));
            #pragma unroll
            for (int m = 0; m < KY; ++m)
                #pragma unroll
                for (int d = 0; d < 4; ++d) acc[m] += w0[d]*v[m+d];
        }
        {   // col x-1, rows Y-4..Y+6 (8-tap)
            float v[KY+7];
            #pragma unroll
            for (int t = 0; t < KY+7; ++t) v[t] = __ldg(hy + (Y-4+t) * HYC + (x-1));
            #pragma unroll
            for (int m = 0; m < KY; ++m)
                #pragma unroll
                for (int t = 0; t < 8; ++t) acc[m] += hh[t]*v[m+t];
        }
        {   // col x, rows Y-2..Y+4
            float v[KY+3];
            #pragma unroll
            for (int t = 0; t < KY+3; ++t) v[t] = __ldg(hy + (Y-2+t) * HYC + x);
            #pragma unroll
            for (int m = 0; m < KY; ++m)
                #pragma unroll
                for (int d = 0; d < 4; ++d) acc[m] += w2[d]*v[m+d];
        }

        // ---- S2 (Hx), row-wise, subtracted ----
        {   // row Y-2: w0 over cols x-2..x+1 (output m=0 only)
            #pragma unroll
            for (int d = 0; d < 4; ++d)
                acc[0] -= w0[d] * __ldg(hx + (Y-2) * HXC + (x-2+d));
        }
        #pragma unroll
        for (int ro = -1; ro <= 2; ++ro) {   // rows Y-1..Y+2, cols x-4..x+3
            float v[8];
            #pragma unroll
            for (int t = 0; t < 8; ++t) v[t] = __ldg(hx + (Y+ro) * HXC + (x-4+t));
            const int m8 = ro + 1;
            #pragma unroll
            for (int t = 0; t < 8; ++t) acc[m8] -= hh[t]*v[t];
            if (ro <= 1) {
                #pragma unroll
                for (int d = 0; d < 4; ++d) acc[ro+2] -= w0[d]*v[d+2];
            }
            if (ro >= 0) {
                #pragma unroll
                for (int d = 0; d < 4; ++d) acc[ro] -= w2[d]*v[d+2];
            }
        }
        {   // row Y+3: w2 over cols x-2..x+1 (output m=3 only)
            #pragma unroll
            for (int d = 0; d < 4; ++d)
                acc[3] -= w2[d] * __ldg(hx + (Y+3) * HXC + (x-2+d));
        }
    } else {
        const float kf[4] = {KF0, KF1, KF2, KF3};
        const float kb[4] = {KB0, KB1, KB2, KB3};
        #pragma unroll
        for (int m = 0; m < KY; ++m) {
            const int y = Y + m;
            float s = 0.0f;
            // S1
            if (y >= 2 && y <= P-3 && x >= 2 && x <= Q-3) {
                float a = 0.0f;
                #pragma unroll
                for (int di = 0; di < 4; ++di)
                    #pragma unroll
                    for (int dj = 0; dj < 3; ++dj)
                        a += __ldg(hy + (y-2+di) * HYC + (x-2+dj)) * f[dj][di];
                s += 0.5f * a;
            }
            if (x >= 1 && x <= Q-2) {
                if (y <= P-5) {
                    float t = 0.0f;
                    #pragma unroll
                    for (int d = 0; d < 4; ++d) t += __ldg(hy + (y+d) * HYC + (x-1)) * kf[d];
                    s += t;
                }
                if (y >= 4) {
                    float t = 0.0f;
                    #pragma unroll
                    for (int d = 0; d < 4; ++d) t += __ldg(hy + (y-4+d) * HYC + (x-1)) * kb[d];
                    s += t;
                }
            }
            // S2
            if (y >= 2 && y <= P-3 && x >= 2 && x <= Q-3) {
                float a = 0.0f;
                #pragma unroll
                for (int di = 0; di < 3; ++di)
                    #pragma unroll
                    for (int dj = 0; dj < 4; ++dj)
                        a += __ldg(hx + (y-2+di) * HXC + (x-2+dj)) * f[di][dj];
                s -= 0.5f * a;
            }
            if (y >= 1 && y <= P-2) {
                if (x <= Q-5) {
                    float t = 0.0f;
                    #pragma unroll
                    for (int d = 0; d < 4; ++d) t += __ldg(hx + (y-1) * HXC + (x+d)) * kf[d];
                    s -= t;
                }
                if (x >= 4) {
                    float t = 0.0f;
                    #pragma unroll
                    for (int d = 0; d < 4; ++d) t += __ldg(hx + (y-1) * HXC + (x-4+d)) * kb[d];
                    s -= t;
                }
            }
            acc[m] = s;
        }
    }

    const float* e = E + b * Eb;
    float* eo = Eout + b * Eob;
    #pragma unroll
    for (int m = 0; m < KY; ++m)
        eo[(Y+m) * Q + x] = __ldg(e + (Y+m) * Q + x) + acc[m];
}

// ===========================================================================
// faraday: Hx_out[i,j] = Hx[i,j] - S3(E);  Hy_out[i,j] = Hy[i,j] + S4(E)
// Thread (tx,ty): col j = j0+tx, rows i = I..I+3, I = i0 + 4*ty.
// ===========================================================================
__global__ __launch_bounds__(NT) void faraday_ldg(
    const float* __restrict__ E,  int Eb,
    const float* __restrict__ Hx, int Hxb,
    const float* __restrict__ Hy, int Hyb,
    const float* __restrict__ filt,
    float* __restrict__ Hxo, int Hxob,
    float* __restrict__ Hyo, int Hyob)
{
    const int j0 = blockIdx.x * TX;
    const int i0 = blockIdx.y * TROWS;
    const int b  = blockIdx.z;
    const int tx = threadIdx.x, ty = threadIdx.y;

    float f[3][4];
    #pragma unroll
    for (int i = 0; i < 12; ++i) (&f[0][0])[i] = __ldg(filt + i);

    const float* e = E + b * Eb;

    const int I = i0 + ty * KY;
    const int j = j0 + tx;

    const bool interior = (i0 >= 2) && (i0 + TROWS <= P - 3) &&
                          (j0 >= 2) && (j0 + TX <= Q - 3);

    if (interior) {
        const float gg[6] = {
            KB0,
            0.5f*f[1][0] + KB1,
            0.5f*f[1][1] + KF0 + KB2,
            0.5f*f[1][2] + KF1 + KB3,
            0.5f*f[1][3] + KF2,
            KF3
        };
        float w0[4], w2[4];
        #pragma unroll
        for (int d = 0; d < 4; ++d) { w0[d] = 0.5f*f[0][d]; w2[d] = 0.5f*f[2][d]; }

        float aHx[KY] = {0.f,0.f,0.f,0.f};
        float aHy[KY] = {0.f,0.f,0.f,0.f};

        {   // col j-2: rows I..I+5
            float v[KY+2];
            #pragma unroll
            for (int t = 0; t < KY+2; ++t) v[t] = __ldg(e + (I+t) * Q + (j-2));
            #pragma unroll
            for (int m = 0; m < KY; ++m) aHx[m] += gg[0]*v[m+1];
        }
        {   // col j-1: rows I..I+5
            float v[KY+2];
            #pragma unroll
            for (int t = 0; t < KY+2; ++t) v[t] = __ldg(e + (I+t) * Q + (j-1));
            #pragma unroll
            for (int m = 0; m < KY; ++m)
                aHx[m] += gg[1]*v[m+1] + w0[0]*v[m] + w2[0]*v[m+2];
        }
        {   // col j: rows I-1..I+5
            float v[KY+3];
            #pragma unroll
            for (int t = 0; t < KY+3; ++t) v[t] = __ldg(e + (I-1+t) * Q + j);
            #pragma unroll
            for (int m = 0; m < KY; ++m) {
                aHx[m] += gg[2]*v[m+2] + w0[1]*v[m+1] + w2[1]*v[m+3];
                #pragma unroll
                for (int d = 0; d < 4; ++d) aHy[m] += w0[d]*v[m+d];
            }
        }
        {   // col j+1: rows I-2..I+6
            float v[KY+5];
            #pragma unroll
            for (int t = 0; t < KY+5; ++t) v[t] = __ldg(e + (I-2+t) * Q + (j+1));
            #pragma unroll
            for (int m = 0; m < KY; ++m) {
                aHx[m] += gg[3]*v[m+3] + w0[2]*v[m+2] + w2[2]*v[m+4];
                #pragma unroll
                for (int t = 0; t < 6; ++t) aHy[m] += gg[t]*v[m+t];
            }
        }
        {   // col j+2: rows I-1..I+5
            float v[KY+3];
            #pragma unroll
            for (int t = 0; t < KY+3; ++t) v[t] = __ldg(e + (I-1+t) * Q + (j+2));
            #pragma unroll
            for (int m = 0; m < KY; ++m) {
                aHx[m] += gg[4]*v[m+2] + w0[3]*v[m+1] + w2[3]*v[m+3];
                #pragma unroll
                for (int d = 0; d < 4; ++d) aHy[m] += w2[d]*v[m+d];
            }
        }
        {   // col j+3: rows I..I+5
            float v[KY+2];
            #pragma unroll
            for (int t = 0; t < KY+2; ++t) v[t] = __ldg(e + (I+t) * Q + (j+3));
            #pragma unroll
            for (int m = 0; m < KY; ++m) aHx[m] += gg[5]*v[m+1];
        }

        const float* hxi = Hx + b * Hxb;
        const float* hyi = Hy + b * Hyb;
        float* hxo = Hxo + b * Hxob;
        float* hyo = Hyo + b * Hyob;
        #pragma unroll
        for (int m = 0; m < KY; ++m) {
            const int i = I + m;
            hxo[i * HXC + j] = __ldg(hxi + i * HXC + j) - aHx[m];
            hyo[i * HYC + j] = __ldg(hyi + i * HYC + j) + aHy[m];
        }
    } else {
        const float kf[4] = {KF0, KF1, KF2, KF3};
        const float kb[4] = {KB0, KB1, KB2, KB3};
        #pragma unroll
        for (int m = 0; m < KY; ++m) {
            const int i = I + m;
            // Hx update: i in [0,HXR), j in [0,HXC)
            if (i < HXR && j < HXC) {
                float s = __ldg(Hx + b * Hxb + i * HXC + j);
                if (j >= 1 && j <= Q-3) {
                    float a = 0.0f;
                    #pragma unroll
                    for (int di = 0; di < 3; ++di)
                        #pragma unroll
                        for (int dj = 0; dj < 4; ++dj)
                            a += __ldg(e + (i+di) * Q + (j-1+dj)) * f[di][dj];
                    s -= 0.5f * a;
                }
                if (j <= Q-4) {
                    float t = 0.0f;
                    #pragma unroll
                    for (int d = 0; d < 4; ++d) t += __ldg(e + (i+1) * Q + (j+d)) * kf[d];
                    s -= t;
                }
                if (j >= 2) {
                    float t = 0.0f;
                    #pragma unroll
                    for (int d = 0; d < 4; ++d) t += __ldg(e + (i+1) * Q + (j-2+d)) * kb[d];
                    s -= t;
                }
                Hxo[b * Hxob + i * HXC + j] = s;
            }
            // Hy update: i in [0,HYR), j in [0,HYC)
            if (i < HYR && j < HYC) {
                float s = __ldg(Hy + b * Hyb + i * HYC + j);
                if (i >= 1 && i <= P-3) {
                    float a = 0.0f;
                    #pragma unroll
                    for (int di = 0; di < 4; ++di)
                        #pragma unroll
                        for (int dj = 0; dj < 3; ++dj)
                            a += __ldg(e + (i-1+di) * Q + (j+dj)) * f[dj][di];
                    s += 0.5f * a;
                }
                if (i <= P-4) {
                    float t = 0.0f;
                    #pragma unroll
                    for (int d = 0; d < 4; ++d) t += __ldg(e + (i+d) * Q + (j+1)) * kf[d];
                    s += t;
                }
                if (i >= 2) {
                    float t = 0.0f;
                    #pragma unroll
                    for (int d = 0; d < 4; ++d) t += __ldg(e + (i-2+d) * Q + (j+1)) * kb[d];
                    s += t;
                }
                Hyo[b * Hyob + i * HYC + j] = s;
            }
        }
    }
}

// ---------------------------------------------------------------------------
// Launch: 2 time steps, results written directly into d_out sections.
// d_out layout:
//   E  : BATCH x (2*P) x Q       @ 0
//   Hx : BATCH x (2*HXR) x HXC   @ BATCH*2*P*Q
//   Hy : BATCH x (2*HYR) x HYC   @ BATCH*2*P*Q + BATCH*2*HXR*HXC
// ---------------------------------------------------------------------------
extern "C" void kernel_launch(void* const* d_in, const int* in_sizes, int n_in,
                              void* d_out, int out_size)
{
    const float* E    = (const float*)d_in[0];
    const float* Hx   = (const float*)d_in[1];
    const float* Hy   = (const float*)d_in[2];
    const float* filt = (const float*)d_in[3];
    float* out = (float*)d_out;

    const int E_IN_B  = P * Q;
    const int HX_IN_B = HXR * HXC;
    const int HY_IN_B = HYR * HYC;

    const int E_OUT_B  = 2 * P * Q;
    const int HX_OUT_B = 2 * HXR * HXC;
    const int HY_OUT_B = 2 * HYR * HYC;

    float* En  = out;
    float* Em  = out + P * Q;
    float* Hxn = out + (long long)BATCH * E_OUT_B;
    float* Hxm = Hxn + HXR * HXC;
    float* Hyn = Hxn + (long long)BATCH * HX_OUT_B;
    float* Hym = Hyn + HYR * HYC;

    dim3 blk(TX, WY, 1);
    dim3 g(Q / TX, P / TROWS, BATCH);   // (32, 32, 8)

    // Step 1
    amper_ldg<<<g, blk>>>(E, E_IN_B, Hx, HX_IN_B, Hy, HY_IN_B, filt,
                          En, E_OUT_B);
    faraday_ldg<<<g, blk>>>(En, E_OUT_B, Hx, HX_IN_B, Hy, HY_IN_B, filt,
                            Hxn, HX_OUT_B, Hyn, HY_OUT_B);
    // Step 2
    amper_ldg<<<g, blk>>>(En, E_OUT_B, Hxn, HX_OUT_B, Hyn, HY_OUT_B, filt,
                          Em, E_OUT_B);
    faraday_ldg<<<g, blk>>>(Em, E_OUT_B, Hxn, HX_OUT_B, Hyn, HY_OUT_B, filt,
                            Hxm, HX_OUT_B, Hym, HY_OUT_B);
}

// round 16
// speedup vs baseline: 1.0119x; 1.0107x over previous
#include <cuda_runtime.h>

// Problem constants (fixed by setup_inputs)
#define BATCH 8
#define P 1024
#define Q 1024
#define HXR (P-2)   // 1022
#define HXC (Q-1)   // 1023
#define HYR (P-1)   // 1023
#define HYC (Q-2)   // 1022

#define TX 32       // tile cols (blockDim.x)
#define WY 8        // blockDim.y
#define KY 4        // outputs per thread (y)
#define TROWS (WY*KY)   // 32 tile rows
#define NT (TX*WY)      // 256 threads
#define MINBLK 6        // 1536 thr/SM, 42-reg budget: unlock LDG batching (MLP)

// KF = 0.5 * [-11/6, 3, -3/2, 1/3] ; KB = -0.5 * reversed
#define KF0 (-11.0f/12.0f)
#define KF1 ( 1.5f)
#define KF2 (-0.75f)
#define KF3 ( 1.0f/6.0f)
#define KB0 (-1.0f/6.0f)
#define KB1 ( 0.75f)
#define KB2 (-1.5f)
#define KB3 ( 11.0f/12.0f)

// ===========================================================================
// amper: E_out[y,x] = E[y,x] + S1(Hy) - S2(Hx)
// Thread (tx,ty): col x = x0+tx, rows y = Y..Y+3, Y = y0 + 4*ty.
// Direct L1 loads; no shared memory, no barrier.
// ===========================================================================
__global__ __launch_bounds__(NT, MINBLK) void amper_ldg(
    const float* __restrict__ E,  int Eb,
    const float* __restrict__ Hx, int Hxb,
    const float* __restrict__ Hy, int Hyb,
    const float* __restrict__ filt,
    float* __restrict__ Eout, int Eob)
{
    const int x0 = blockIdx.x * TX;
    const int y0 = blockIdx.y * TROWS;
    const int b  = blockIdx.z;
    const int tx = threadIdx.x, ty = threadIdx.y;

    float f[3][4];
    #pragma unroll
    for (int i = 0; i < 12; ++i) (&f[0][0])[i] = __ldg(filt + i);

    const float* hy = Hy + b * Hyb;
    const float* hx = Hx + b * Hxb;

    const int Y = y0 + ty * KY;
    const int x = x0 + tx;

    const bool interior = (y0 >= 4) && (y0 + TROWS <= P - 4) &&
                          (x0 >= 2) && (x0 + TX <= Q - 2);

    float acc[KY] = {0.f, 0.f, 0.f, 0.f};

    if (interior) {
        const float hh[8] = {
            KB0, KB1,
            0.5f*f[1][0] + KB2, 0.5f*f[1][1] + KB3,
            0.5f*f[1][2] + KF0, 0.5f*f[1][3] + KF1,
            KF2, KF3
        };
        float w0[4], w2[4];
        #pragma unroll
        for (int d = 0; d < 4; ++d) { w0[d] = 0.5f*f[0][d]; w2[d] = 0.5f*f[2][d]; }

        // ---- S1 (Hy), column-wise, added ----
        {   // col x-2, rows Y-2..Y+4
            float v[KY+3];
            #pragma unroll
            for (int t = 0; t < KY+3; ++t) v[t] = __ldg(hy + (Y-2+t) * HYC + (x-2));
            #pragma unroll
            for (int m = 0; m < KY; ++m)
                #pragma unroll
                for (int d = 0; d < 4; ++d) acc[m] += w0[d]*v[m+d];
        }
        {   // col x-1, rows Y-4..Y+6 (8-tap)
            float v[KY+7];
            #pragma unroll
            for (int t = 0; t < KY+7; ++t) v[t] = __ldg(hy + (Y-4+t) * HYC + (x-1));
            #pragma unroll
            for (int m = 0; m < KY; ++m)
                #pragma unroll
                for (int t = 0; t < 8; ++t) acc[m] += hh[t]*v[m+t];
        }
        {   // col x, rows Y-2..Y+4
            float v[KY+3];
            #pragma unroll
            for (int t = 0; t < KY+3; ++t) v[t] = __ldg(hy + (Y-2+t) * HYC + x);
            #pragma unroll
            for (int m = 0; m < KY; ++m)
                #pragma unroll
                for (int d = 0; d < 4; ++d) acc[m] += w2[d]*v[m+d];
        }

        // ---- S2 (Hx), row-wise, subtracted ----
        {   // row Y-2: w0 over cols x-2..x+1 (output m=0 only)
            #pragma unroll
            for (int d = 0; d < 4; ++d)
                acc[0] -= w0[d] * __ldg(hx + (Y-2) * HXC + (x-2+d));
        }
        #pragma unroll
        for (int ro = -1; ro <= 2; ++ro) {   // rows Y-1..Y+2, cols x-4..x+3
            float v[8];
            #pragma unroll
            for (int t = 0; t < 8; ++t) v[t] = __ldg(hx + (Y+ro) * HXC + (x-4+t));
            const int m8 = ro + 1;
            #pragma unroll
            for (int t = 0; t < 8; ++t) acc[m8] -= hh[t]*v[t];
            if (ro <= 1) {
                #pragma unroll
                for (int d = 0; d < 4; ++d) acc[ro+2] -= w0[d]*v[d+2];
            }
            if (ro >= 0) {
                #pragma unroll
                for (int d = 0; d < 4; ++d) acc[ro] -= w2[d]*v[d+2];
            }
        }
        {   // row Y+3: w2 over cols x-2..x+1 (output m=3 only)
            #pragma unroll
            for (int d = 0; d < 4; ++d)
                acc[3] -= w2[d] * __ldg(hx + (Y+3) * HXC + (x-2+d));
        }
    } else {
        const float kf[4] = {KF0, KF1, KF2, KF3};
        const float kb[4] = {KB0, KB1, KB2, KB3};
        #pragma unroll
        for (int m = 0; m < KY; ++m) {
            const int y = Y + m;
            float s = 0.0f;
            // S1
            if (y >= 2 && y <= P-3 && x >= 2 && x <= Q-3) {
                float a = 0.0f;
                #pragma unroll
                for (int di = 0; di < 4; ++di)
                    #pragma unroll
                    for (int dj = 0; dj < 3; ++dj)
                        a += __ldg(hy + (y-2+di) * HYC + (x-2+dj)) * f[dj][di];
                s += 0.5f * a;
            }
            if (x >= 1 && x <= Q-2) {
                if (y <= P-5) {
                    float t = 0.0f;
                    #pragma unroll
                    for (int d = 0; d < 4; ++d) t += __ldg(hy + (y+d) * HYC + (x-1)) * kf[d];
                    s += t;
                }
                if (y >= 4) {
                    float t = 0.0f;
                    #pragma unroll
                    for (int d = 0; d < 4; ++d) t += __ldg(hy + (y-4+d) * HYC + (x-1)) * kb[d];
                    s += t;
                }
            }
            // S2
            if (y >= 2 && y <= P-3 && x >= 2 && x <= Q-3) {
                float a = 0.0f;
                #pragma unroll
                for (int di = 0; di < 3; ++di)
                    #pragma unroll
                    for (int dj = 0; dj < 4; ++dj)
                        a += __ldg(hx + (y-2+di) * HXC + (x-2+dj)) * f[di][dj];
                s -= 0.5f * a;
            }
            if (y >= 1 && y <= P-2) {
                if (x <= Q-5) {
                    float t = 0.0f;
                    #pragma unroll
                    for (int d = 0; d < 4; ++d) t += __ldg(hx + (y-1) * HXC + (x+d)) * kf[d];
                    s -= t;
                }
                if (x >= 4) {
                    float t = 0.0f;
                    #pragma unroll
                    for (int d = 0; d < 4; ++d) t += __ldg(hx + (y-1) * HXC + (x-4+d)) * kb[d];
                    s -= t;
                }
            }
            acc[m] = s;
        }
    }

    const float* e = E + b * Eb;
    float* eo = Eout + b * Eob;
    #pragma unroll
    for (int m = 0; m < KY; ++m)
        eo[(Y+m) * Q + x] = __ldg(e + (Y+m) * Q + x) + acc[m];
}

// ===========================================================================
// faraday: Hx_out[i,j] = Hx[i,j] - S3(E);  Hy_out[i,j] = Hy[i,j] + S4(E)
// Thread (tx,ty): col j = j0+tx, rows i = I..I+3, I = i0 + 4*ty.
// ===========================================================================
__global__ __launch_bounds__(NT, MINBLK) void faraday_ldg(
    const float* __restrict__ E,  int Eb,
    const float* __restrict__ Hx, int Hxb,
    const float* __restrict__ Hy, int Hyb,
    const float* __restrict__ filt,
    float* __restrict__ Hxo, int Hxob,
    float* __restrict__ Hyo, int Hyob)
{
    const int j0 = blockIdx.x * TX;
    const int i0 = blockIdx.y * TROWS;
    const int b  = blockIdx.z;
    const int tx = threadIdx.x, ty = threadIdx.y;

    float f[3][4];
    #pragma unroll
    for (int i = 0; i < 12; ++i) (&f[0][0])[i] = __ldg(filt + i);

    const float* e = E + b * Eb;

    const int I = i0 + ty * KY;
    const int j = j0 + tx;

    const bool interior = (i0 >= 2) && (i0 + TROWS <= P - 3) &&
                          (j0 >= 2) && (j0 + TX <= Q - 3);

    if (interior) {
        const float gg[6] = {
            KB0,
            0.5f*f[1][0] + KB1,
            0.5f*f[1][1] + KF0 + KB2,
            0.5f*f[1][2] + KF1 + KB3,
            0.5f*f[1][3] + KF2,
            KF3
        };
        float w0[4], w2[4];
        #pragma unroll
        for (int d = 0; d < 4; ++d) { w0[d] = 0.5f*f[0][d]; w2[d] = 0.5f*f[2][d]; }

        float aHx[KY] = {0.f,0.f,0.f,0.f};
        float aHy[KY] = {0.f,0.f,0.f,0.f};

        {   // col j-2: rows I..I+5
            float v[KY+2];
            #pragma unroll
            for (int t = 0; t < KY+2; ++t) v[t] = __ldg(e + (I+t) * Q + (j-2));
            #pragma unroll
            for (int m = 0; m < KY; ++m) aHx[m] += gg[0]*v[m+1];
        }
        {   // col j-1: rows I..I+5
            float v[KY+2];
            #pragma unroll
            for (int t = 0; t < KY+2; ++t) v[t] = __ldg(e + (I+t) * Q + (j-1));
            #pragma unroll
            for (int m = 0; m < KY; ++m)
                aHx[m] += gg[1]*v[m+1] + w0[0]*v[m] + w2[0]*v[m+2];
        }
        {   // col j: rows I-1..I+5
            float v[KY+3];
            #pragma unroll
            for (int t = 0; t < KY+3; ++t) v[t] = __ldg(e + (I-1+t) * Q + j);
            #pragma unroll
            for (int m = 0; m < KY; ++m) {
                aHx[m] += gg[2]*v[m+2] + w0[1]*v[m+1] + w2[1]*v[m+3];
                #pragma unroll
                for (int d = 0; d < 4; ++d) aHy[m] += w0[d]*v[m+d];
            }
        }
        {   // col j+1: rows I-2..I+6
            float v[KY+5];
            #pragma unroll
            for (int t = 0; t < KY+5; ++t) v[t] = __ldg(e + (I-2+t) * Q + (j+1));
            #pragma unroll
            for (int m = 0; m < KY; ++m) {
                aHx[m] += gg[3]*v[m+3] + w0[2]*v[m+2] + w2[2]*v[m+4];
                #pragma unroll
                for (int t = 0; t < 6; ++t) aHy[m] += gg[t]*v[m+t];
            }
        }
        {   // col j+2: rows I-1..I+5
            float v[KY+3];
            #pragma unroll
            for (int t = 0; t < KY+3; ++t) v[t] = __ldg(e + (I-1+t) * Q + (j+2));
            #pragma unroll
            for (int m = 0; m < KY; ++m) {
                aHx[m] += gg[4]*v[m+2] + w0[3]*v[m+1] + w2[3]*v[m+3];
                #pragma unroll
                for (int d = 0; d < 4; ++d) aHy[m] += w2[d]*v[m+d];
            }
        }
        {   // col j+3: rows I..I+5
            float v[KY+2];
            #pragma unroll
            for (int t = 0; t < KY+2; ++t) v[t] = __ldg(e + (I+t) * Q + (j+3));
            #pragma unroll
            for (int m = 0; m < KY; ++m) aHx[m] += gg[5]*v[m+1];
        }

        const float* hxi = Hx + b * Hxb;
        const float* hyi = Hy + b * Hyb;
        float* hxo = Hxo + b * Hxob;
        float* hyo = Hyo + b * Hyob;
        #pragma unroll
        for (int m = 0; m < KY; ++m) {
            const int i = I + m;
            hxo[i * HXC + j] = __ldg(hxi + i * HXC + j) - aHx[m];
            hyo[i * HYC + j] = __ldg(hyi + i * HYC + j) + aHy[m];
        }
    } else {
        const float kf[4] = {KF0, KF1, KF2, KF3};
        const float kb[4] = {KB0, KB1, KB2, KB3};
        #pragma unroll
        for (int m = 0; m < KY; ++m) {
            const int i = I + m;
            // Hx update: i in [0,HXR), j in [0,HXC)
            if (i < HXR && j < HXC) {
                float s = __ldg(Hx + b * Hxb + i * HXC + j);
                if (j >= 1 && j <= Q-3) {
                    float a = 0.0f;
                    #pragma unroll
                    for (int di = 0; di < 3; ++di)
                        #pragma unroll
                        for (int dj = 0; dj < 4; ++dj)
                            a += __ldg(e + (i+di) * Q + (j-1+dj)) * f[di][dj];
                    s -= 0.5f * a;
                }
                if (j <= Q-4) {
                    float t = 0.0f;
                    #pragma unroll
                    for (int d = 0; d < 4; ++d) t += __ldg(e + (i+1) * Q + (j+d)) * kf[d];
                    s -= t;
                }
                if (j >= 2) {
                    float t = 0.0f;
                    #pragma unroll
                    for (int d = 0; d < 4; ++d) t += __ldg(e + (i+1) * Q + (j-2+d)) * kb[d];
                    s -= t;
                }
                Hxo[b * Hxob + i * HXC + j] = s;
            }
            // Hy update: i in [0,HYR), j in [0,HYC)
            if (i < HYR && j < HYC) {
                float s = __ldg(Hy + b * Hyb + i * HYC + j);
                if (i >= 1 && i <= P-3) {
                    float a = 0.0f;
                    #pragma unroll
                    for (int di = 0; di < 4; ++di)
                        #pragma unroll
                        for (int dj = 0; dj < 3; ++dj)
                            a += __ldg(e + (i-1+di) * Q + (j+dj)) * f[dj][di];
                    s += 0.5f * a;
                }
                if (i <= P-4) {
                    float t = 0.0f;
                    #pragma unroll
                    for (int d = 0; d < 4; ++d) t += __ldg(e + (i+d) * Q + (j+1)) * kf[d];
                    s += t;
                }
                if (i >= 2) {
                    float t = 0.0f;
                    #pragma unroll
                    for (int d = 0; d < 4; ++d) t += __ldg(e + (i-2+d) * Q + (j+1)) * kb[d];
                    s += t;
                }
                Hyo[b * Hyob + i * HYC + j] = s;
            }
        }
    }
}

// ---------------------------------------------------------------------------
// Launch: 2 time steps, results written directly into d_out sections.
// d_out layout:
//   E  : BATCH x (2*P) x Q       @ 0
//   Hx : BATCH x (2*HXR) x HXC   @ BATCH*2*P*Q
//   Hy : BATCH x (2*HYR) x HYC   @ BATCH*2*P*Q + BATCH*2*HXR*HXC
// ---------------------------------------------------------------------------
extern "C" void kernel_launch(void* const* d_in, const int* in_sizes, int n_in,
                              void* d_out, int out_size)
{
    const float* E    = (const float*)d_in[0];
    const float* Hx   = (const float*)d_in[1];
    const float* Hy   = (const float*)d_in[2];
    const float* filt = (const float*)d_in[3];
    float* out = (float*)d_out;

    const int E_IN_B  = P * Q;
    const int HX_IN_B = HXR * HXC;
    const int HY_IN_B = HYR * HYC;

    const int E_OUT_B  = 2 * P * Q;
    const int HX_OUT_B = 2 * HXR * HXC;
    const int HY_OUT_B = 2 * HYR * HYC;

    float* En  = out;
    float* Em  = out + P * Q;
    float* Hxn = out + (long long)BATCH * E_OUT_B;
    float* Hxm = Hxn + HXR * HXC;
    float* Hyn = Hxn + (long long)BATCH * HX_OUT_B;
    float* Hym = Hyn + HYR * HYC;

    dim3 blk(TX, WY, 1);
    dim3 g(Q / TX, P / TROWS, BATCH);   // (32, 32, 8)

    // Step 1
    amper_ldg<<<g, blk>>>(E, E_IN_B, Hx, HX_IN_B, Hy, HY_IN_B, filt,
                          En, E_OUT_B);
    faraday_ldg<<<g, blk>>>(En, E_OUT_B, Hx, HX_IN_B, Hy, HY_IN_B, filt,
                            Hxn, HX_OUT_B, Hyn, HY_OUT_B);
    // Step 2
    amper_ldg<<<g, blk>>>(En, E_OUT_B, Hxn, HX_OUT_B, Hyn, HY_OUT_B, filt,
                          Em, E_OUT_B);
    faraday_ldg<<<g, blk>>>(Em, E_OUT_B, Hxn, HX_OUT_B, Hyn, HY_OUT_B, filt,
                            Hxm, HX_OUT_B, Hym, HY_OUT_B);
}